// round 5
// baseline (speedup 1.0000x reference)
#include <cuda_runtime.h>
#include <math.h>
#include <stdint.h>

#define NB 65536
#define ND 768
#define NS 64
#define NT 17
#define T_MAX 2.0f
#define DT (T_MAX / (float)NT)
#define EPSV 1e-8f

#define KC 32                 // k columns per chunk
#define NCHUNK (ND / KC)      // 24
#define STG 5                 // ring stages
#define STAGE_BYTES (256 * KC * 4)   // 32 KB
#define SM_TOTAL (STG * STAGE_BYTES)

typedef unsigned long long ull;

// ---------------- device scratch ----------------
__device__ float  g_projT[NS * NB];            // proj transposed [s][b]
__device__ float4 g_dirsFrag[(ND / 8) * 4 * 32]; // tf32 A fragments
__device__ float  g_dirinv[NS];
__device__ float  g_colsum[ND];
__device__ float  g_colsq[ND];
__device__ float  g_psum[NS];
__device__ float  g_psq[NS];
__device__ float  g_pmean[NS];
__device__ float  g_pinvstd[NS];
__device__ float  g_ecfr[NT * NS];
__device__ float  g_ecfi[NT * NS];

// ---------------- ptx helpers ----------------
__device__ __forceinline__ uint32_t f2tf(float f) {
    uint32_t r; asm("cvt.rna.tf32.f32 %0, %1;" : "=r"(r) : "f"(f)); return r;
}
__device__ __forceinline__ void mma8(float* c, const uint32_t* a,
                                     uint32_t b0, uint32_t b1) {
    asm volatile(
        "mma.sync.aligned.m16n8k8.row.col.f32.tf32.tf32.f32 "
        "{%0,%1,%2,%3},{%4,%5,%6,%7},{%8,%9},{%0,%1,%2,%3};"
        : "+f"(c[0]), "+f"(c[1]), "+f"(c[2]), "+f"(c[3])
        : "r"(a[0]), "r"(a[1]), "r"(a[2]), "r"(a[3]), "r"(b0), "r"(b1));
}
__device__ __forceinline__ uint32_t smem_u32(const void* p) {
    uint32_t a;
    asm("{ .reg .u64 t; cvta.to.shared.u64 t, %1; cvt.u32.u64 %0, t; }" : "=r"(a) : "l"(p));
    return a;
}
__device__ __forceinline__ void cp16(uint32_t s, const void* g) {
    asm volatile("cp.async.cg.shared.global [%0], [%1], 16;" :: "r"(s), "l"(g));
}
#define CP_COMMIT() asm volatile("cp.async.commit_group;" ::: "memory")
#define CP_WAIT()   asm volatile("cp.async.wait_group %0;" :: "n"(STG - 1) : "memory")

// packed f32x2 helpers
__device__ __forceinline__ ull pack2(float lo, float hi) {
    ull r; asm("mov.b64 %0, {%1, %2};" : "=l"(r) : "f"(lo), "f"(hi)); return r;
}
__device__ __forceinline__ void fma2(ull& d, ull a, ull b) {
    asm("fma.rn.f32x2 %0, %1, %2, %0;" : "+l"(d) : "l"(a), "l"(b));
}
__device__ __forceinline__ ull mul2(ull a, ull b) {
    ull r; asm("mul.rn.f32x2 %0, %1, %2;" : "=l"(r) : "l"(a), "l"(b)); return r;
}
__device__ __forceinline__ ull add2(ull a, ull b) {
    ull r; asm("add.rn.f32x2 %0, %1, %2;" : "=l"(r) : "l"(a), "l"(b)); return r;
}
__device__ __forceinline__ float2 unpk(ull v) {
    float2 f; asm("mov.b64 {%0, %1}, %2;" : "=f"(f.x), "=f"(f.y) : "l"(v)); return f;
}

// ---------------- kernel 0: zero accumulators (graph replayed) -------------
__global__ void k_init() {
    int i = blockIdx.x * blockDim.x + threadIdx.x;
    if (i < ND)      { g_colsum[i] = 0.f; g_colsq[i] = 0.f; }
    if (i < NS)      { g_psum[i]   = 0.f; g_psq[i]   = 0.f; }
    if (i < NT * NS) { g_ecfr[i]   = 0.f; g_ecfi[i]  = 0.f; }
}

// ---------------- kernel 1: direction column inverse norms ----------------
__global__ void k_dirnorm(const float* __restrict__ dirs) {
    int s = threadIdx.x;            // 64
    float acc = 0.f;
    for (int d = 0; d < ND; d++) {
        float v = dirs[d * NS + s];
        acc += v * v;
    }
    g_dirinv[s] = 1.0f / sqrtf(acc);
}

// ---------------- kernel 1b: build tf32 A fragments ------------------------
__global__ void k_prepfrag(const float* __restrict__ dirs) {
    int idx = blockIdx.x * blockDim.x + threadIdx.x;   // 48*256 = 12288
    int kk = idx >> 7, rem = idx & 127;
    int mt = rem >> 5, lane = rem & 31;
    int g = lane >> 2, t = lane & 3;
    int s0 = mt * 16 + g;
    int k0 = kk * 8 + t;
    float i0 = g_dirinv[s0], i1 = g_dirinv[s0 + 8];
    float4 v;
    v.x = __uint_as_float(f2tf(dirs[(size_t)k0 * NS + s0]       * i0));
    v.y = __uint_as_float(f2tf(dirs[(size_t)k0 * NS + s0 + 8]   * i1));
    v.z = __uint_as_float(f2tf(dirs[(size_t)(k0 + 4) * NS + s0]     * i0));
    v.w = __uint_as_float(f2tf(dirs[(size_t)(k0 + 4) * NS + s0 + 8] * i1));
    g_dirsFrag[idx] = v;
}

// ---------------- kernel 3: fused HMMA tf32 GEMM + colstats + psums --------
// Block: 256 rows of z x all 64 s. z staged via cp.async ring in
// column-group-major layout [(col/4)][row][col%4] -> conflict-free frag LDS.
// Fuses per-dim (colstats) and per-s (psum/psq) statistics.
__global__ __launch_bounds__(256, 1) void k_gemm(const float* __restrict__ z) {
    extern __shared__ __align__(16) char smem[];
    __shared__ float scol_s[ND], scol_q[ND];
    __shared__ float ssum[64], ssq[64];

    const uint32_t sbase = smem_u32(smem);
    const int tid = threadIdx.x;
    const int wid = tid >> 5, lane = tid & 31;
    const int g = lane >> 2, t = lane & 3;
    const int brow0 = blockIdx.x * 256;

    for (int i = tid; i < ND; i += 256) { scol_s[i] = 0.f; scol_q[i] = 0.f; }
    if (tid < 64) { ssum[tid] = 0.f; ssq[tid] = 0.f; }
    __syncthreads();

    // ---- stage filler: thread tid fills (c=j, r=tid) for j=0..7 ----
    const float* zrow = z + (size_t)(brow0 + tid) * ND;
    #define LOAD_CHUNK(ch) do { \
        uint32_t dst = sbase + ((ch) % STG) * STAGE_BYTES + tid * 16; \
        const float* src = zrow + (ch) * KC; \
        _Pragma("unroll") \
        for (int j = 0; j < 8; j++) \
            cp16(dst + j * 4096, src + j * 4); \
        CP_COMMIT(); \
    } while (0)

    #pragma unroll
    for (int ch = 0; ch < STG; ch++) LOAD_CHUNK(ch);

    float c[4][4][4];
    #pragma unroll
    for (int mt = 0; mt < 4; mt++)
        #pragma unroll
        for (int nt = 0; nt < 4; nt++)
            #pragma unroll
            for (int r = 0; r < 4; r++) c[mt][nt][r] = 0.f;

    for (int ch = 0; ch < NCHUNK; ch++) {
        CP_WAIT();
        __syncthreads();
        const uint32_t stage = sbase + (ch % STG) * STAGE_BYTES;

        #pragma unroll
        for (int kk = 0; kk < 4; kk++) {          // local k-steps of 8
            const int kg = ch * 4 + kk;
            uint32_t a[4][4];
            #pragma unroll
            for (int mt = 0; mt < 4; mt++) {
                float4 v = __ldg(&g_dirsFrag[kg * 128 + mt * 32 + lane]);
                a[mt][0] = __float_as_uint(v.x);
                a[mt][1] = __float_as_uint(v.y);
                a[mt][2] = __float_as_uint(v.z);
                a[mt][3] = __float_as_uint(v.w);
            }
            float vb0[4], vb1[4];
            #pragma unroll
            for (int nt = 0; nt < 4; nt++) {
                int lr = wid * 32 + nt * 8 + g;
                uint32_t o0 = stage + ((2 * kk + 0) * 256 + lr) * 16 + t * 4;
                uint32_t o1 = stage + ((2 * kk + 1) * 256 + lr) * 16 + t * 4;
                asm volatile("ld.shared.f32 %0, [%1];" : "=f"(vb0[nt]) : "r"(o0));
                asm volatile("ld.shared.f32 %0, [%1];" : "=f"(vb1[nt]) : "r"(o1));
            }
            // fused colstats
            float cs0 = vb0[0] + vb0[1] + vb0[2] + vb0[3];
            float cs1 = vb1[0] + vb1[1] + vb1[2] + vb1[3];
            float cq0 = vb0[0]*vb0[0] + vb0[1]*vb0[1] + vb0[2]*vb0[2] + vb0[3]*vb0[3];
            float cq1 = vb1[0]*vb1[0] + vb1[1]*vb1[1] + vb1[2]*vb1[2] + vb1[3]*vb1[3];
            #pragma unroll
            for (int off = 4; off < 32; off <<= 1) {
                cs0 += __shfl_xor_sync(0xffffffffu, cs0, off);
                cs1 += __shfl_xor_sync(0xffffffffu, cs1, off);
                cq0 += __shfl_xor_sync(0xffffffffu, cq0, off);
                cq1 += __shfl_xor_sync(0xffffffffu, cq1, off);
            }
            if (lane < 4) {
                atomicAdd(&scol_s[kg * 8 + t],     cs0);
                atomicAdd(&scol_q[kg * 8 + t],     cq0);
                atomicAdd(&scol_s[kg * 8 + t + 4], cs1);
                atomicAdd(&scol_q[kg * 8 + t + 4], cq1);
            }
            // MMA
            uint32_t b0[4], b1[4];
            #pragma unroll
            for (int nt = 0; nt < 4; nt++) { b0[nt] = f2tf(vb0[nt]); b1[nt] = f2tf(vb1[nt]); }
            #pragma unroll
            for (int mt = 0; mt < 4; mt++)
                #pragma unroll
                for (int nt = 0; nt < 4; nt++)
                    mma8(c[mt][nt], a[mt], b0[nt], b1[nt]);
        }

        __syncthreads();                 // stage fully consumed
        if (ch + STG < NCHUNK) LOAD_CHUNK(ch + STG);
    }

    // ---- epilogue: projT store + fused per-s sums ----
    int nbase = brow0 + wid * 32;
    #pragma unroll
    for (int mt = 0; mt < 4; mt++) {
        float su0 = 0.f, su1 = 0.f, sq0 = 0.f, sq1 = 0.f;
        int s0 = mt * 16 + g;
        #pragma unroll
        for (int nt = 0; nt < 4; nt++) {
            float d0 = c[mt][nt][0], d1 = c[mt][nt][1];
            float d2 = c[mt][nt][2], d3 = c[mt][nt][3];
            int n = nbase + nt * 8 + t * 2;
            *(float2*)(g_projT + (size_t)s0 * NB + n)       = make_float2(d0, d1);
            *(float2*)(g_projT + (size_t)(s0 + 8) * NB + n) = make_float2(d2, d3);
            su0 += d0 + d1; sq0 += d0 * d0 + d1 * d1;
            su1 += d2 + d3; sq1 += d2 * d2 + d3 * d3;
        }
        #pragma unroll
        for (int off = 1; off < 4; off <<= 1) {
            su0 += __shfl_xor_sync(0xffffffffu, su0, off);
            sq0 += __shfl_xor_sync(0xffffffffu, sq0, off);
            su1 += __shfl_xor_sync(0xffffffffu, su1, off);
            sq1 += __shfl_xor_sync(0xffffffffu, sq1, off);
        }
        if (t == 0) {
            atomicAdd(&ssum[s0], su0);     atomicAdd(&ssq[s0], sq0);
            atomicAdd(&ssum[s0 + 8], su1); atomicAdd(&ssq[s0 + 8], sq1);
        }
    }
    __syncthreads();
    if (tid < 64) {
        atomicAdd(&g_psum[tid], ssum[tid]);
        atomicAdd(&g_psq[tid],  ssq[tid]);
    }
    for (int i = tid; i < ND; i += 256) {
        atomicAdd(&g_colsum[i], scol_s[i]);
        atomicAdd(&g_colsq[i],  scol_q[i]);
    }
}

// ---------------- kernel 5: finalize proj mean/invstd ----------------------
__global__ void k_pfinal() {
    int s = threadIdx.x;  // 64
    float mean = g_psum[s] / (float)NB;
    float var = (g_psq[s] - (float)NB * mean * mean) / (float)(NB - 1);
    g_pmean[s] = mean;
    g_pinvstd[s] = 1.0f / (sqrtf(fmaxf(var, 0.f)) + EPSV);
}

// ---------------- kernel 6: ECF via packed f32x2 rotation ------------------
__global__ __launch_bounds__(256) void k_ecf() {
    int s = blockIdx.y;
    float mean = g_pmean[s], invstd = g_pinvstd[s];
    size_t basep = (size_t)s * NB + blockIdx.x * 4096;
    const float2* src = (const float2*)(g_projT + basep);

    ull CR[NT], CI[NT];
    #pragma unroll
    for (int j = 0; j < NT; j++) { CR[j] = 0ull; CI[j] = 0ull; }

    #pragma unroll 2
    for (int i = 0; i < 8; i++) {
        float2 pv = src[threadIdx.x + i * 256];
        float p0 = (pv.x - mean) * invstd;
        float p1 = (pv.y - mean) * invstd;
        float c0, s0, c1v, s1v;
        __sincosf(DT * p0, &s0, &c0);
        __sincosf(DT * p1, &s1v, &c1v);
        ull cP  = pack2(c0, c1v);
        ull sP  = pack2(s0, s1v);
        ull nsP = pack2(-s0, -s1v);
        ull ck = cP, sk = sP;
        #pragma unroll
        for (int j = 0; j < NT; j++) {
            CR[j] = add2(CR[j], ck);
            CI[j] = add2(CI[j], sk);
            ull cn = mul2(ck, cP); fma2(cn, sk, nsP);  // ck*c - sk*s
            ull sn = mul2(sk, cP); fma2(sn, ck, sP);   // sk*c + ck*s
            ck = cn; sk = sn;
        }
    }

    unsigned msk = 0xffffffffu;
    #pragma unroll
    for (int j = 0; j < NT; j++) {
        float2 r2 = unpk(CR[j]);
        float2 i2 = unpk(CI[j]);
        float r = r2.x + r2.y, im = i2.x + i2.y;
        #pragma unroll
        for (int off = 16; off; off >>= 1) {
            r  += __shfl_down_sync(msk, r,  off);
            im += __shfl_down_sync(msk, im, off);
        }
        if ((threadIdx.x & 31) == 0) {
            atomicAdd(&g_ecfr[j * NS + s], r);
            atomicAdd(&g_ecfi[j * NS + s], im);
        }
    }
}

// ---------------- kernel 7: final scalar loss -------------------------------
__global__ __launch_bounds__(256) void k_final(float* __restrict__ out) {
    __shared__ float red[256];
    int t = threadIdx.x;
    float acc = 0.f;

    for (int d = t; d < ND; d += 256) {
        float mean = g_colsum[d] / (float)NB;
        float var = (g_colsq[d] - (float)NB * mean * mean) / (float)(NB - 1);
        float stdv = sqrtf(fmaxf(var, 0.f));
        acc += fmaxf(1.0f - stdv, 0.f) * (1.0f / (float)ND);
    }

    for (int idx = t; idx < NT * NS; idx += 256) {
        int j = idx / NS;
        float tj = DT * (float)(j + 1);
        float er = g_ecfr[idx] / (float)NB;
        float ei = g_ecfi[idx] / (float)NB;
        float tcf = expf(-0.5f * tj * tj);
        float term = er * er + ei * ei - 2.0f * er * tcf + tcf * tcf;
        float w = DT * ((j == 0 || j == NT - 1) ? 0.5f : 1.0f);
        acc += w * term * (1.0f / (float)NS);
    }

    red[t] = acc;
    __syncthreads();
    for (int off = 128; off; off >>= 1) {
        if (t < off) red[t] += red[t + off];
        __syncthreads();
    }
    if (t == 0) out[0] = red[0];
}

// ---------------- launch -----------------------------------------------------
extern "C" void kernel_launch(void* const* d_in, const int* in_sizes, int n_in,
                              void* d_out, int out_size) {
    const float* z    = (const float*)d_in[0];   // [65536, 768]
    const float* dirs = (const float*)d_in[1];   // [768, 64]
    float* out = (float*)d_out;

    cudaFuncSetAttribute(k_gemm, cudaFuncAttributeMaxDynamicSharedMemorySize, SM_TOTAL);

    k_init<<<5, 256>>>();
    k_dirnorm<<<1, 64>>>(dirs);
    k_prepfrag<<<48, 256>>>(dirs);
    k_gemm<<<NB / 256, 256, SM_TOTAL>>>(z);
    k_pfinal<<<1, NS>>>();
    k_ecf<<<dim3(16, NS), 256>>>();
    k_final<<<1, 256>>>(out);
}

// round 6
// speedup vs baseline: 1.3723x; 1.3723x over previous
#include <cuda_runtime.h>
#include <math.h>
#include <stdint.h>

#define NB 65536
#define ND 768
#define NS 64
#define NT 17
#define T_MAX 2.0f
#define DT (T_MAX / (float)NT)
#define EPSV 1e-8f
#define NKK (ND / 8)   // 96 k-steps of 8

typedef unsigned long long ull;

// ---------------- device scratch ----------------
__device__ float  g_projT[NS * NB];         // proj transposed [s][b]
__device__ float4 g_dirsFrag[NKK * 4 * 32]; // A fragments, tf32, frag-ready
__device__ float  g_dirinv[NS];
__device__ float  g_colsum[ND];
__device__ float  g_colsq[ND];
__device__ float  g_psum[NS];
__device__ float  g_psq[NS];
__device__ float  g_pmean[NS];
__device__ float  g_pinvstd[NS];
__device__ float  g_ecfr[NT * NS];
__device__ float  g_ecfi[NT * NS];

// ---------------- ptx helpers ----------------
__device__ __forceinline__ uint32_t f2tf(float f) {
    uint32_t r; asm("cvt.rna.tf32.f32 %0, %1;" : "=r"(r) : "f"(f)); return r;
}
__device__ __forceinline__ void mma8(float* c, const uint32_t* a,
                                     uint32_t b0, uint32_t b1) {
    asm volatile(
        "mma.sync.aligned.m16n8k8.row.col.f32.tf32.tf32.f32 "
        "{%0,%1,%2,%3},{%4,%5,%6,%7},{%8,%9},{%0,%1,%2,%3};"
        : "+f"(c[0]), "+f"(c[1]), "+f"(c[2]), "+f"(c[3])
        : "r"(a[0]), "r"(a[1]), "r"(a[2]), "r"(a[3]), "r"(b0), "r"(b1));
}

// packed f32x2 helpers
__device__ __forceinline__ ull pack2(float lo, float hi) {
    ull r; asm("mov.b64 %0, {%1, %2};" : "=l"(r) : "f"(lo), "f"(hi)); return r;
}
__device__ __forceinline__ void fma2(ull& d, ull a, ull b) {
    asm("fma.rn.f32x2 %0, %1, %2, %0;" : "+l"(d) : "l"(a), "l"(b));
}
__device__ __forceinline__ ull mul2(ull a, ull b) {
    ull r; asm("mul.rn.f32x2 %0, %1, %2;" : "=l"(r) : "l"(a), "l"(b)); return r;
}
__device__ __forceinline__ ull add2(ull a, ull b) {
    ull r; asm("add.rn.f32x2 %0, %1, %2;" : "=l"(r) : "l"(a), "l"(b)); return r;
}
__device__ __forceinline__ float2 unpk(ull v) {
    float2 f; asm("mov.b64 {%0, %1}, %2;" : "=f"(f.x), "=f"(f.y) : "l"(v)); return f;
}

// ---------------- kernel 0: zero accumulators (graph replayed) -------------
__global__ void k_init() {
    int i = blockIdx.x * blockDim.x + threadIdx.x;
    if (i < ND)      { g_colsum[i] = 0.f; g_colsq[i] = 0.f; }
    if (i < NS)      { g_psum[i]   = 0.f; g_psq[i]   = 0.f; }
    if (i < NT * NS) { g_ecfr[i]   = 0.f; g_ecfi[i]  = 0.f; }
}

// ---------------- kernel 1: direction column inverse norms ----------------
__global__ void k_dirnorm(const float* __restrict__ dirs) {
    int s = threadIdx.x;            // 64
    float acc = 0.f;
    #pragma unroll 8
    for (int d = 0; d < ND; d++) {
        float v = dirs[d * NS + s];
        acc += v * v;
    }
    g_dirinv[s] = 1.0f / sqrtf(acc);
}

// ---------------- kernel 1b: build tf32 A fragments ------------------------
__global__ void k_prepfrag(const float* __restrict__ dirs) {
    int idx = blockIdx.x * blockDim.x + threadIdx.x;   // 48*256 = 12288
    int kk = idx >> 7, rem = idx & 127;
    int mt = rem >> 5, lane = rem & 31;
    int g = lane >> 2, t = lane & 3;
    int s0 = mt * 16 + g;
    int k0 = kk * 8 + t;
    float i0 = g_dirinv[s0], i1 = g_dirinv[s0 + 8];
    float4 v;
    v.x = __uint_as_float(f2tf(dirs[(size_t)k0 * NS + s0]       * i0));
    v.y = __uint_as_float(f2tf(dirs[(size_t)k0 * NS + s0 + 8]   * i1));
    v.z = __uint_as_float(f2tf(dirs[(size_t)(k0 + 4) * NS + s0]     * i0));
    v.w = __uint_as_float(f2tf(dirs[(size_t)(k0 + 4) * NS + s0 + 8] * i1));
    g_dirsFrag[idx] = v;
}

// ---------------- kernel 3: HMMA tf32 GEMM + fused colstats + psums --------
// Warp computes M=64 x 32 batch cols straight from global (each z element
// read exactly once). Colstats: per k-step, reduce B-frags over nt (regs),
// over g (shuffles), then plain STS into per-warp smem slice (each slot
// written exactly once). No mainloop syncs or atomics.
__global__ __launch_bounds__(256, 2) void k_gemm(const float* __restrict__ z) {
    extern __shared__ float scol[];             // [2][8][768]: sum, sq
    __shared__ float ssum[64], ssq[64];
    float* scol_s = scol;
    float* scol_q = scol + 8 * ND;

    int tid = threadIdx.x;
    int wid = tid >> 5, lane = tid & 31;
    int g = lane >> 2, t = lane & 3;

    if (tid < 64) { ssum[tid] = 0.f; ssq[tid] = 0.f; }
    __syncthreads();

    int nbase = blockIdx.x * 256 + wid * 32;          // warp's batch base
    const float* zb = z + (size_t)(nbase + g) * ND + t;
    float* myrow_s = scol_s + wid * ND;
    float* myrow_q = scol_q + wid * ND;

    float c[4][4][4];
    #pragma unroll
    for (int mt = 0; mt < 4; mt++)
        #pragma unroll
        for (int nt = 0; nt < 4; nt++)
            #pragma unroll
            for (int r = 0; r < 4; r++) c[mt][nt][r] = 0.f;

    for (int kk = 0; kk < NKK; kk++) {
        uint32_t a[4][4];
        #pragma unroll
        for (int mt = 0; mt < 4; mt++) {
            float4 v = g_dirsFrag[kk * 128 + mt * 32 + lane];
            a[mt][0] = __float_as_uint(v.x);
            a[mt][1] = __float_as_uint(v.y);
            a[mt][2] = __float_as_uint(v.z);
            a[mt][3] = __float_as_uint(v.w);
        }
        float v0[4], v1[4];
        #pragma unroll
        for (int nt = 0; nt < 4; nt++) {
            v0[nt] = __ldg(zb + (size_t)nt * 8 * ND + kk * 8);
            v1[nt] = __ldg(zb + (size_t)nt * 8 * ND + kk * 8 + 4);
        }
        // fused colstats: reduce over nt, then over g (lanes stride 4)
        float cs0 = (v0[0] + v0[1]) + (v0[2] + v0[3]);
        float cs1 = (v1[0] + v1[1]) + (v1[2] + v1[3]);
        float cq0 = v0[0]*v0[0] + v0[1]*v0[1] + v0[2]*v0[2] + v0[3]*v0[3];
        float cq1 = v1[0]*v1[0] + v1[1]*v1[1] + v1[2]*v1[2] + v1[3]*v1[3];
        #pragma unroll
        for (int off = 4; off < 32; off <<= 1) {
            cs0 += __shfl_xor_sync(0xffffffffu, cs0, off);
            cs1 += __shfl_xor_sync(0xffffffffu, cs1, off);
            cq0 += __shfl_xor_sync(0xffffffffu, cq0, off);
            cq1 += __shfl_xor_sync(0xffffffffu, cq1, off);
        }
        if (lane < 4) {                 // each (warp, col) written exactly once
            myrow_s[kk * 8 + t]     = cs0;
            myrow_q[kk * 8 + t]     = cq0;
            myrow_s[kk * 8 + 4 + t] = cs1;
            myrow_q[kk * 8 + 4 + t] = cq1;
        }
        // MMA
        uint32_t b0[4], b1[4];
        #pragma unroll
        for (int nt = 0; nt < 4; nt++) { b0[nt] = f2tf(v0[nt]); b1[nt] = f2tf(v1[nt]); }
        #pragma unroll
        for (int mt = 0; mt < 4; mt++)
            #pragma unroll
            for (int nt = 0; nt < 4; nt++)
                mma8(c[mt][nt], a[mt], b0[nt], b1[nt]);
    }

    // epilogue: store projT + fused per-s sums
    #pragma unroll
    for (int mt = 0; mt < 4; mt++) {
        float su0 = 0.f, su1 = 0.f, sq0 = 0.f, sq1 = 0.f;
        int s0 = mt * 16 + g;
        #pragma unroll
        for (int nt = 0; nt < 4; nt++) {
            float d0 = c[mt][nt][0], d1 = c[mt][nt][1];
            float d2 = c[mt][nt][2], d3 = c[mt][nt][3];
            int n = nbase + nt * 8 + t * 2;
            *(float2*)(g_projT + (size_t)s0 * NB + n)       = make_float2(d0, d1);
            *(float2*)(g_projT + (size_t)(s0 + 8) * NB + n) = make_float2(d2, d3);
            su0 += d0 + d1; sq0 += d0 * d0 + d1 * d1;
            su1 += d2 + d3; sq1 += d2 * d2 + d3 * d3;
        }
        #pragma unroll
        for (int off = 1; off < 4; off <<= 1) {
            su0 += __shfl_xor_sync(0xffffffffu, su0, off);
            sq0 += __shfl_xor_sync(0xffffffffu, sq0, off);
            su1 += __shfl_xor_sync(0xffffffffu, su1, off);
            sq1 += __shfl_xor_sync(0xffffffffu, sq1, off);
        }
        if (t == 0) {
            atomicAdd(&ssum[s0], su0);     atomicAdd(&ssq[s0], sq0);
            atomicAdd(&ssum[s0 + 8], su1); atomicAdd(&ssq[s0 + 8], sq1);
        }
    }
    __syncthreads();
    if (tid < 64) {
        atomicAdd(&g_psum[tid], ssum[tid]);
        atomicAdd(&g_psq[tid],  ssq[tid]);
    }
    // colstats flush: reduce 8 warp slices, one atomic per (block, col)
    #pragma unroll
    for (int rep = 0; rep < 3; rep++) {
        int col = rep * 256 + tid;
        float s = 0.f, q = 0.f;
        #pragma unroll
        for (int w = 0; w < 8; w++) {
            s += scol_s[w * ND + col];
            q += scol_q[w * ND + col];
        }
        atomicAdd(&g_colsum[col], s);
        atomicAdd(&g_colsq[col],  q);
    }
}

// ---------------- kernel 5: finalize proj mean/invstd ----------------------
__global__ void k_pfinal() {
    int s = threadIdx.x;  // 64
    float mean = g_psum[s] / (float)NB;
    float var = (g_psq[s] - (float)NB * mean * mean) / (float)(NB - 1);
    g_pmean[s] = mean;
    g_pinvstd[s] = 1.0f / (sqrtf(fmaxf(var, 0.f)) + EPSV);
}

// ---------------- kernel 6: ECF via packed f32x2 rotation ------------------
__global__ __launch_bounds__(256) void k_ecf() {
    int s = blockIdx.y;
    float mean = g_pmean[s], invstd = g_pinvstd[s];
    size_t basep = (size_t)s * NB + blockIdx.x * 4096;
    const float2* src = (const float2*)(g_projT + basep);

    ull CR[NT], CI[NT];
    #pragma unroll
    for (int j = 0; j < NT; j++) { CR[j] = 0ull; CI[j] = 0ull; }

    #pragma unroll 2
    for (int i = 0; i < 8; i++) {
        float2 pv = src[threadIdx.x + i * 256];
        float p0 = (pv.x - mean) * invstd;
        float p1 = (pv.y - mean) * invstd;
        float c0, s0, c1v, s1v;
        __sincosf(DT * p0, &s0, &c0);
        __sincosf(DT * p1, &s1v, &c1v);
        ull cP  = pack2(c0, c1v);
        ull sP  = pack2(s0, s1v);
        ull nsP = pack2(-s0, -s1v);
        ull ck = cP, sk = sP;
        #pragma unroll
        for (int j = 0; j < NT; j++) {
            CR[j] = add2(CR[j], ck);
            CI[j] = add2(CI[j], sk);
            ull cn = mul2(ck, cP); fma2(cn, sk, nsP);  // ck*c - sk*s
            ull sn = mul2(sk, cP); fma2(sn, ck, sP);   // sk*c + ck*s
            ck = cn; sk = sn;
        }
    }

    unsigned msk = 0xffffffffu;
    #pragma unroll
    for (int j = 0; j < NT; j++) {
        float2 r2 = unpk(CR[j]);
        float2 i2 = unpk(CI[j]);
        float r = r2.x + r2.y, im = i2.x + i2.y;
        #pragma unroll
        for (int off = 16; off; off >>= 1) {
            r  += __shfl_down_sync(msk, r,  off);
            im += __shfl_down_sync(msk, im, off);
        }
        if ((threadIdx.x & 31) == 0) {
            atomicAdd(&g_ecfr[j * NS + s], r);
            atomicAdd(&g_ecfi[j * NS + s], im);
        }
    }
}

// ---------------- kernel 7: final scalar loss -------------------------------
__global__ __launch_bounds__(256) void k_final(float* __restrict__ out) {
    __shared__ float red[256];
    int t = threadIdx.x;
    float acc = 0.f;

    for (int d = t; d < ND; d += 256) {
        float mean = g_colsum[d] / (float)NB;
        float var = (g_colsq[d] - (float)NB * mean * mean) / (float)(NB - 1);
        float stdv = sqrtf(fmaxf(var, 0.f));
        acc += fmaxf(1.0f - stdv, 0.f) * (1.0f / (float)ND);
    }

    for (int idx = t; idx < NT * NS; idx += 256) {
        int j = idx / NS;
        float tj = DT * (float)(j + 1);
        float er = g_ecfr[idx] / (float)NB;
        float ei = g_ecfi[idx] / (float)NB;
        float tcf = expf(-0.5f * tj * tj);
        float term = er * er + ei * ei - 2.0f * er * tcf + tcf * tcf;
        float w = DT * ((j == 0 || j == NT - 1) ? 0.5f : 1.0f);
        acc += w * term * (1.0f / (float)NS);
    }

    red[t] = acc;
    __syncthreads();
    for (int off = 128; off; off >>= 1) {
        if (t < off) red[t] += red[t + off];
        __syncthreads();
    }
    if (t == 0) out[0] = red[0];
}

// ---------------- launch -----------------------------------------------------
extern "C" void kernel_launch(void* const* d_in, const int* in_sizes, int n_in,
                              void* d_out, int out_size) {
    const float* z    = (const float*)d_in[0];   // [65536, 768]
    const float* dirs = (const float*)d_in[1];   // [768, 64]
    float* out = (float*)d_out;

    const int scol_bytes = 2 * 8 * ND * sizeof(float);   // 48 KB
    cudaFuncSetAttribute(k_gemm, cudaFuncAttributeMaxDynamicSharedMemorySize, scol_bytes);

    k_init<<<5, 256>>>();
    k_dirnorm<<<1, 64>>>(dirs);
    k_prepfrag<<<48, 256>>>(dirs);
    k_gemm<<<NB / 256, 256, scol_bytes>>>(z);
    k_pfinal<<<1, NS>>>();
    k_ecf<<<dim3(16, NS), 256>>>();
    k_final<<<1, 256>>>(out);
}

// round 7
// speedup vs baseline: 2.2151x; 1.6142x over previous
#include <cuda_runtime.h>
#include <math.h>
#include <stdint.h>

#define NB 65536
#define ND 768
#define NS 64
#define NT 17
#define T_MAX 2.0f
#define DT (T_MAX / (float)NT)
#define EPSV 1e-8f
#define NCH 24                 // k chunks of 32
#define NKK (ND / 8)           // 96

typedef unsigned long long ull;

// ---------------- device scratch ----------------
__device__ float  g_projT[NS * NB];
__device__ float4 g_dirsFrag[NKK * 4 * 32];
__device__ float  g_norm2[NS];
__device__ float  g_colsum[ND];
__device__ float  g_colsq[ND];
__device__ float  g_psum[NS];
__device__ float  g_psq[NS];
__device__ float  g_pmean[NS];
__device__ float  g_pinvstd[NS];
__device__ float  g_ecfr[NT * NS];
__device__ float  g_ecfi[NT * NS];

// ---------------- ptx helpers ----------------
__device__ __forceinline__ uint32_t f2tf(float f) {
    uint32_t r; asm("cvt.rna.tf32.f32 %0, %1;" : "=r"(r) : "f"(f)); return r;
}
__device__ __forceinline__ void mma8(float* c, const uint32_t* a,
                                     uint32_t b0, uint32_t b1) {
    asm volatile(
        "mma.sync.aligned.m16n8k8.row.col.f32.tf32.tf32.f32 "
        "{%0,%1,%2,%3},{%4,%5,%6,%7},{%8,%9},{%0,%1,%2,%3};"
        : "+f"(c[0]), "+f"(c[1]), "+f"(c[2]), "+f"(c[3])
        : "r"(a[0]), "r"(a[1]), "r"(a[2]), "r"(a[3]), "r"(b0), "r"(b1));
}
__device__ __forceinline__ uint32_t smem_u32(const void* p) {
    uint32_t a;
    asm("{ .reg .u64 t; cvta.to.shared.u64 t, %1; cvt.u32.u64 %0, t; }" : "=r"(a) : "l"(p));
    return a;
}
__device__ __forceinline__ void cp16(uint32_t s, const void* g) {
    asm volatile("cp.async.cg.shared.global [%0], [%1], 16;" :: "r"(s), "l"(g));
}
#define CP_COMMIT() asm volatile("cp.async.commit_group;" ::: "memory")
#define CP_WAIT1()  asm volatile("cp.async.wait_group 1;" ::: "memory")
#define CP_WAIT0()  asm volatile("cp.async.wait_group 0;" ::: "memory")
__device__ __forceinline__ float lds32(uint32_t a) {
    float v; asm volatile("ld.shared.f32 %0, [%1];" : "=f"(v) : "r"(a)); return v;
}

// packed f32x2 helpers
__device__ __forceinline__ ull pack2(float lo, float hi) {
    ull r; asm("mov.b64 %0, {%1, %2};" : "=l"(r) : "f"(lo), "f"(hi)); return r;
}
__device__ __forceinline__ void fma2(ull& d, ull a, ull b) {
    asm("fma.rn.f32x2 %0, %1, %2, %0;" : "+l"(d) : "l"(a), "l"(b));
}
__device__ __forceinline__ ull mul2(ull a, ull b) {
    ull r; asm("mul.rn.f32x2 %0, %1, %2;" : "=l"(r) : "l"(a), "l"(b)); return r;
}
__device__ __forceinline__ ull add2(ull a, ull b) {
    ull r; asm("add.rn.f32x2 %0, %1, %2;" : "=l"(r) : "l"(a), "l"(b)); return r;
}
__device__ __forceinline__ float2 unpk(ull v) {
    float2 f; asm("mov.b64 {%0, %1}, %2;" : "=f"(f.x), "=f"(f.y) : "l"(v)); return f;
}

// ---------------- kernel 0: zero accumulators (graph replayed) -------------
__global__ void k_init() {
    int i = blockIdx.x * blockDim.x + threadIdx.x;
    if (i < ND)      { g_colsum[i] = 0.f; g_colsq[i] = 0.f; }
    if (i < NS)      { g_psum[i]   = 0.f; g_psq[i]   = 0.f; g_norm2[i] = 0.f; }
    if (i < NT * NS) { g_ecfr[i]   = 0.f; g_ecfi[i]  = 0.f; }
}

// ---------------- kernel 1: dir column norms (parallel, coalesced) --------
// Block b covers d in [b*12, b*12+12). Thread: s = tid&63, dq = tid>>6.
__global__ __launch_bounds__(256) void k_dirnorm(const float* __restrict__ dirs) {
    __shared__ float red[4][64];
    int s = threadIdx.x & 63, dq = threadIdx.x >> 6;
    int d0 = blockIdx.x * 12;
    float acc = 0.f;
    #pragma unroll
    for (int j = 0; j < 3; j++) {
        float v = dirs[(size_t)(d0 + j * 4 + dq) * NS + s];
        acc += v * v;
    }
    red[dq][s] = acc;
    __syncthreads();
    if (threadIdx.x < 64) {
        float v = red[0][s] + red[1][s] + red[2][s] + red[3][s];
        atomicAdd(&g_norm2[s], v);
    }
}

// ---------------- kernel 1b: build tf32 A fragments ------------------------
__global__ void k_prepfrag(const float* __restrict__ dirs) {
    int idx = blockIdx.x * blockDim.x + threadIdx.x;   // 48*256 = 12288
    int kk = idx >> 7, rem = idx & 127;
    int mt = rem >> 5, lane = rem & 31;
    int g = lane >> 2, t = lane & 3;
    int s0 = mt * 16 + g;
    int k0 = kk * 8 + t;
    float i0 = 1.0f / sqrtf(g_norm2[s0]);
    float i1 = 1.0f / sqrtf(g_norm2[s0 + 8]);
    float4 v;
    v.x = __uint_as_float(f2tf(dirs[(size_t)k0 * NS + s0]       * i0));
    v.y = __uint_as_float(f2tf(dirs[(size_t)k0 * NS + s0 + 8]   * i1));
    v.z = __uint_as_float(f2tf(dirs[(size_t)(k0 + 4) * NS + s0]     * i0));
    v.w = __uint_as_float(f2tf(dirs[(size_t)(k0 + 4) * NS + s0 + 8] * i1));
    g_dirsFrag[idx] = v;
}

// ---------------- kernel 3: staged HMMA tf32 GEMM + colstats + psums -------
// Per-warp 2-stage cp.async ring (SW128-swizzled, 4KB/stage). No block syncs
// in the mainloop. Colstats via column-per-lane smem re-read (no shuffles).
__global__ __launch_bounds__(256, 2) void k_gemm(const float* __restrict__ z) {
    extern __shared__ __align__(128) char smem[];      // [8][2][4096] stages
    __shared__ float scol_s[ND], scol_q[ND];
    __shared__ float ssum[64], ssq[64];

    const uint32_t sb = smem_u32(smem);
    const int tid = threadIdx.x;
    const int wid = tid >> 5, lane = tid & 31;
    const int g = lane >> 2, t = lane & 3;
    const int nwarp = blockIdx.x * 256 + wid * 32;     // warp's 32 batch rows

    for (int i = tid; i < ND; i += 256) { scol_s[i] = 0.f; scol_q[i] = 0.f; }
    if (tid < 64) { ssum[tid] = 0.f; ssq[tid] = 0.f; }
    __syncthreads();

    const uint32_t wstage = sb + wid * 8192;           // 2 stages x 4KB
    // cp fill mapping: instr i: row r = i*4 + (lane>>3), unit u = lane&7
    const int fr = lane >> 3, fu = lane & 7;
    const float* zsrc = z + (size_t)nwarp * ND;

    #define FILL(ch, st) do { \
        uint32_t dst = wstage + (st) * 4096; \
        const float* srcb = zsrc + (ch) * 32; \
        _Pragma("unroll") \
        for (int i = 0; i < 8; i++) { \
            int r = i * 4 + fr; \
            cp16(dst + r * 128 + ((fu ^ (r & 7)) << 4), \
                 srcb + (size_t)r * ND + fu * 4); \
        } \
        CP_COMMIT(); \
    } while (0)

    FILL(0, 0);
    FILL(1, 1);

    float c[4][4][4];
    #pragma unroll
    for (int mt = 0; mt < 4; mt++)
        #pragma unroll
        for (int nt = 0; nt < 4; nt++)
            #pragma unroll
            for (int r = 0; r < 4; r++) c[mt][nt][r] = 0.f;

    for (int ch = 0; ch < NCH; ch++) {
        if (ch < NCH - 1) { CP_WAIT1(); } else { CP_WAIT0(); }
        __syncwarp();
        const uint32_t stage = wstage + (ch & 1) * 4096;

        #pragma unroll
        for (int kk = 0; kk < 4; kk++) {
            const int kg = ch * 4 + kk;
            uint32_t a[4][4];
            #pragma unroll
            for (int mt = 0; mt < 4; mt++) {
                float4 v = __ldg(&g_dirsFrag[kg * 128 + mt * 32 + lane]);
                a[mt][0] = __float_as_uint(v.x);
                a[mt][1] = __float_as_uint(v.y);
                a[mt][2] = __float_as_uint(v.z);
                a[mt][3] = __float_as_uint(v.w);
            }
            uint32_t b0[4], b1[4];
            #pragma unroll
            for (int nt = 0; nt < 4; nt++) {
                int row = nt * 8 + g;
                uint32_t base = stage + row * 128 + t * 4;
                b0[nt] = f2tf(lds32(base + (((2 * kk)     ^ g) << 4)));
                b1[nt] = f2tf(lds32(base + (((2 * kk + 1) ^ g) << 4)));
            }
            #pragma unroll
            for (int mt = 0; mt < 4; mt++)
                #pragma unroll
                for (int nt = 0; nt < 4; nt++)
                    mma8(c[mt][nt], a[mt], b0[nt], b1[nt]);
        }

        // colstats: lane owns column (ch*32 + lane), sums warp's 32 rows
        {
            const int cu = lane >> 2, co = (lane & 3) * 4;
            float cs = 0.f, cq = 0.f;
            #pragma unroll
            for (int r = 0; r < 32; r++) {
                float v = lds32(stage + r * 128 + ((cu ^ (r & 7)) << 4) + co);
                cs += v; cq += v * v;
            }
            atomicAdd(&scol_s[ch * 32 + lane], cs);
            atomicAdd(&scol_q[ch * 32 + lane], cq);
        }
        __syncwarp();
        if (ch + 2 < NCH) FILL(ch + 2, ch & 1);
    }

    // epilogue: projT store + fused per-s sums
    #pragma unroll
    for (int mt = 0; mt < 4; mt++) {
        float su0 = 0.f, su1 = 0.f, sq0 = 0.f, sq1 = 0.f;
        int s0 = mt * 16 + g;
        #pragma unroll
        for (int nt = 0; nt < 4; nt++) {
            float d0 = c[mt][nt][0], d1 = c[mt][nt][1];
            float d2 = c[mt][nt][2], d3 = c[mt][nt][3];
            int n = nwarp + nt * 8 + t * 2;
            *(float2*)(g_projT + (size_t)s0 * NB + n)       = make_float2(d0, d1);
            *(float2*)(g_projT + (size_t)(s0 + 8) * NB + n) = make_float2(d2, d3);
            su0 += d0 + d1; sq0 += d0 * d0 + d1 * d1;
            su1 += d2 + d3; sq1 += d2 * d2 + d3 * d3;
        }
        #pragma unroll
        for (int off = 1; off < 4; off <<= 1) {
            su0 += __shfl_xor_sync(0xffffffffu, su0, off);
            sq0 += __shfl_xor_sync(0xffffffffu, sq0, off);
            su1 += __shfl_xor_sync(0xffffffffu, su1, off);
            sq1 += __shfl_xor_sync(0xffffffffu, sq1, off);
        }
        if (t == 0) {
            atomicAdd(&ssum[s0], su0);     atomicAdd(&ssq[s0], sq0);
            atomicAdd(&ssum[s0 + 8], su1); atomicAdd(&ssq[s0 + 8], sq1);
        }
    }
    __syncthreads();
    if (tid < 64) {
        atomicAdd(&g_psum[tid], ssum[tid]);
        atomicAdd(&g_psq[tid],  ssq[tid]);
    }
    #pragma unroll
    for (int rep = 0; rep < 3; rep++) {
        int col = rep * 256 + tid;
        atomicAdd(&g_colsum[col], scol_s[col]);
        atomicAdd(&g_colsq[col],  scol_q[col]);
    }
}

// ---------------- kernel 5: finalize proj mean/invstd ----------------------
__global__ void k_pfinal() {
    int s = threadIdx.x;  // 64
    float mean = g_psum[s] / (float)NB;
    float var = (g_psq[s] - (float)NB * mean * mean) / (float)(NB - 1);
    g_pmean[s] = mean;
    g_pinvstd[s] = 1.0f / (sqrtf(fmaxf(var, 0.f)) + EPSV);
}

// ---------------- kernel 6: ECF via packed f32x2 rotation ------------------
__global__ __launch_bounds__(256) void k_ecf() {
    int s = blockIdx.y;
    float mean = g_pmean[s], invstd = g_pinvstd[s];
    size_t basep = (size_t)s * NB + blockIdx.x * 4096;
    const float2* src = (const float2*)(g_projT + basep);

    ull CR[NT], CI[NT];
    #pragma unroll
    for (int j = 0; j < NT; j++) { CR[j] = 0ull; CI[j] = 0ull; }

    #pragma unroll 2
    for (int i = 0; i < 8; i++) {
        float2 pv = src[threadIdx.x + i * 256];
        float p0 = (pv.x - mean) * invstd;
        float p1 = (pv.y - mean) * invstd;
        float c0, s0, c1v, s1v;
        __sincosf(DT * p0, &s0, &c0);
        __sincosf(DT * p1, &s1v, &c1v);
        ull cP  = pack2(c0, c1v);
        ull sP  = pack2(s0, s1v);
        ull nsP = pack2(-s0, -s1v);
        ull ck = cP, sk = sP;
        #pragma unroll
        for (int j = 0; j < NT; j++) {
            CR[j] = add2(CR[j], ck);
            CI[j] = add2(CI[j], sk);
            ull cn = mul2(ck, cP); fma2(cn, sk, nsP);
            ull sn = mul2(sk, cP); fma2(sn, ck, sP);
            ck = cn; sk = sn;
        }
    }

    unsigned msk = 0xffffffffu;
    #pragma unroll
    for (int j = 0; j < NT; j++) {
        float2 r2 = unpk(CR[j]);
        float2 i2 = unpk(CI[j]);
        float r = r2.x + r2.y, im = i2.x + i2.y;
        #pragma unroll
        for (int off = 16; off; off >>= 1) {
            r  += __shfl_down_sync(msk, r,  off);
            im += __shfl_down_sync(msk, im, off);
        }
        if ((threadIdx.x & 31) == 0) {
            atomicAdd(&g_ecfr[j * NS + s], r);
            atomicAdd(&g_ecfi[j * NS + s], im);
        }
    }
}

// ---------------- kernel 7: final scalar loss -------------------------------
__global__ __launch_bounds__(256) void k_final(float* __restrict__ out) {
    __shared__ float red[256];
    int t = threadIdx.x;
    float acc = 0.f;

    for (int d = t; d < ND; d += 256) {
        float mean = g_colsum[d] / (float)NB;
        float var = (g_colsq[d] - (float)NB * mean * mean) / (float)(NB - 1);
        float stdv = sqrtf(fmaxf(var, 0.f));
        acc += fmaxf(1.0f - stdv, 0.f) * (1.0f / (float)ND);
    }

    for (int idx = t; idx < NT * NS; idx += 256) {
        int j = idx / NS;
        float tj = DT * (float)(j + 1);
        float er = g_ecfr[idx] / (float)NB;
        float ei = g_ecfi[idx] / (float)NB;
        float tcf = expf(-0.5f * tj * tj);
        float term = er * er + ei * ei - 2.0f * er * tcf + tcf * tcf;
        float w = DT * ((j == 0 || j == NT - 1) ? 0.5f : 1.0f);
        acc += w * term * (1.0f / (float)NS);
    }

    red[t] = acc;
    __syncthreads();
    for (int off = 128; off; off >>= 1) {
        if (t < off) red[t] += red[t + off];
        __syncthreads();
    }
    if (t == 0) out[0] = red[0];
}

// ---------------- launch -----------------------------------------------------
extern "C" void kernel_launch(void* const* d_in, const int* in_sizes, int n_in,
                              void* d_out, int out_size) {
    const float* z    = (const float*)d_in[0];   // [65536, 768]
    const float* dirs = (const float*)d_in[1];   // [768, 64]
    float* out = (float*)d_out;

    const int stage_bytes = 8 * 2 * 4096;   // 64 KB dynamic
    cudaFuncSetAttribute(k_gemm, cudaFuncAttributeMaxDynamicSharedMemorySize, stage_bytes);

    k_init<<<5, 256>>>();
    k_dirnorm<<<64, 256>>>(dirs);
    k_prepfrag<<<48, 256>>>(dirs);
    k_gemm<<<NB / 256, 256, stage_bytes>>>(z);
    k_pfinal<<<1, NS>>>();
    k_ecf<<<dim3(16, NS), 256>>>();
    k_final<<<1, 256>>>(out);
}